// round 4
// baseline (speedup 1.0000x reference)
#include <cuda_runtime.h>

#define NQ 4
#define QDIM 16
#define BB 4
#define SS 512
#define EE 512
#define NROWS (BB*SS)

// Scratch (no allocations allowed):
__device__ __align__(16) float g_q[NROWS * 4];
__device__ __align__(16) float g_k[NROWS * 4];
__device__ __align__(16) float g_v[NROWS * 4];
__device__ float g_C[81];

struct c2 { float x, y; };
__device__ __forceinline__ c2 cmul(c2 a, c2 b) { return {a.x*b.x - a.y*b.y, a.x*b.y + a.y*b.x}; }
__device__ __forceinline__ c2 cadd(c2 a, c2 b) { return {a.x + b.x, a.y + b.y}; }

// Accurate tanh via ex2: arg in (-2,2), exp(2x) in [e^-4,e^4], no overflow.
__device__ __forceinline__ float ftanh(float x) {
    float e2 = __expf(2.0f * x);
    return __fdividef(e2 - 1.0f, e2 + 1.0f);
}

// ---------------------------------------------------------------------------
// Setup: build U (16x16 circuit unitary), A = Re(U^H Z U), collapse to the
// 81-coefficient multilinear tensor C. One block, runs once per launch.
// Wire w <-> bit position (3 - w) (numpy row-major flatten of (2,2,2,2)).
// ---------------------------------------------------------------------------
__global__ void setup_kernel(const float* __restrict__ qw) {
    __shared__ c2 G[8][4];        // 8 Rot gates (layer*4 + wire), 2x2 each
    __shared__ c2 U[QDIM][QDIM];  // U[m][col]
    __shared__ float A[QDIM][QDIM];
    int tid = threadIdx.x;

    if (tid < 8) {
        float a = qw[tid * 3 + 0] * 0.5f;
        float b = qw[tid * 3 + 1] * 0.5f;
        float c = qw[tid * 3 + 2] * 0.5f;
        float ca = cosf(a), sa = sinf(a);
        float cb = cosf(b), sb = sinf(b);
        float zc = cosf(c), zs = sinf(c);
        // RX = [[ca, -i sa], [-i sa, ca]]
        c2 X00 = {ca, 0.f}, X01 = {0.f, -sa}, X10 = {0.f, -sa}, X11 = {ca, 0.f};
        // M = RY @ RX  (RY real)
        c2 M00 = {cb * X00.x - sb * X10.x, cb * X00.y - sb * X10.y};
        c2 M01 = {cb * X01.x - sb * X11.x, cb * X01.y - sb * X11.y};
        c2 M10 = {sb * X00.x + cb * X10.x, sb * X00.y + cb * X10.y};
        c2 M11 = {sb * X01.x + cb * X11.x, sb * X01.y + cb * X11.y};
        // G = RZ @ M, RZ = diag(e^{-ic}, e^{+ic})
        c2 e0 = {zc, -zs}, e1 = {zc, zs};
        G[tid][0] = cmul(e0, M00); G[tid][1] = cmul(e0, M01);
        G[tid][2] = cmul(e1, M10); G[tid][3] = cmul(e1, M11);
    }
    __syncthreads();

    if (tid < QDIM) {
        c2 amp[QDIM];
        #pragma unroll
        for (int d = 0; d < QDIM; d++) amp[d] = {0.f, 0.f};
        amp[tid] = {1.f, 0.f};
        #pragma unroll
        for (int layer = 0; layer < 2; layer++) {
            #pragma unroll
            for (int w = 0; w < 4; w++) {
                c2 g00 = G[layer * 4 + w][0], g01 = G[layer * 4 + w][1];
                c2 g10 = G[layer * 4 + w][2], g11 = G[layer * 4 + w][3];
                int mask = 1 << (3 - w);
                #pragma unroll
                for (int d = 0; d < QDIM; d++) {
                    if (d & mask) continue;
                    c2 x0 = amp[d], x1 = amp[d | mask];
                    amp[d]        = cadd(cmul(g00, x0), cmul(g01, x1));
                    amp[d | mask] = cadd(cmul(g10, x0), cmul(g11, x1));
                }
            }
            // CNOTs (ctrl,tgt): (0,1),(1,2),(2,3),(3,0) -> msb-first bitmasks
            const int cm[4] = {8, 4, 2, 1};
            const int tm[4] = {4, 2, 1, 8};
            #pragma unroll
            for (int p = 0; p < 4; p++) {
                #pragma unroll
                for (int d = 0; d < QDIM; d++) {
                    if ((d & cm[p]) && !(d & tm[p])) {
                        c2 t = amp[d];
                        amp[d] = amp[d | tm[p]];
                        amp[d | tm[p]] = t;
                    }
                }
            }
        }
        #pragma unroll
        for (int m = 0; m < QDIM; m++) U[m][tid] = amp[m];
    }
    __syncthreads();

    // A[d][e] = Re( sum_m conj(U[m][d]) * z_m * U[m][e] ),  z_m = 4 - 2 popc(m)
    {
        int d = tid >> 4, e = tid & 15;
        float s = 0.f;
        #pragma unroll
        for (int m = 0; m < QDIM; m++) {
            float z = 4.0f - 2.0f * (float)__popc(m);
            s += z * (U[m][d].x * U[m][e].x + U[m][d].y * U[m][e].y);
        }
        A[d][e] = s;
    }
    __syncthreads();

    // C[t0..t3], v=(1,cos a,sin a) per wire.
    // t=0: e_w=d_w, coeff 1/2; t=1: e_w=d_w, coeff (+/-)1/2 by d_w; t=2: e_w=1-d_w, 1/2.
    if (tid < 81) {
        int t0 = tid / 27, t1 = (tid / 9) % 3, t2 = (tid / 3) % 3, t3 = tid % 3;
        int tw[4] = {t0, t1, t2, t3};
        int xmask = 0, m1 = 0;
        #pragma unroll
        for (int w = 0; w < 4; w++) {
            if (tw[w] == 2) xmask |= 1 << (3 - w);
            if (tw[w] == 1) m1   |= 1 << (3 - w);
        }
        float s = 0.f;
        #pragma unroll
        for (int d = 0; d < QDIM; d++) {
            float sgn = (__popc(d & m1) & 1) ? -1.0f : 1.0f;
            s += sgn * A[d][d ^ xmask];
        }
        g_C[tid] = s * 0.0625f;  // (1/2)^4
    }
}

// ---------------------------------------------------------------------------
// QKV projection: one block per (b,s) row. q,k get tanh; v linear.
// ---------------------------------------------------------------------------
__global__ void qkv_kernel(const float* __restrict__ x,
                           const float* __restrict__ Wq, const float* __restrict__ bq,
                           const float* __restrict__ Wk, const float* __restrict__ bk,
                           const float* __restrict__ Wv, const float* __restrict__ bv) {
    int row = blockIdx.x;
    int tid = threadIdx.x;  // 128
    const float* xr = x + row * EE;

    float acc[12];
    #pragma unroll
    for (int i = 0; i < 12; i++) acc[i] = 0.f;

    #pragma unroll 2
    for (int e = tid; e < EE; e += 128) {
        float xv = __ldg(xr + e);
        float4 wq = __ldg((const float4*)(Wq + e * 4));
        float4 wk = __ldg((const float4*)(Wk + e * 4));
        float4 wv = __ldg((const float4*)(Wv + e * 4));
        acc[0] += xv * wq.x; acc[1] += xv * wq.y; acc[2]  += xv * wq.z; acc[3]  += xv * wq.w;
        acc[4] += xv * wk.x; acc[5] += xv * wk.y; acc[6]  += xv * wk.z; acc[7]  += xv * wk.w;
        acc[8] += xv * wv.x; acc[9] += xv * wv.y; acc[10] += xv * wv.z; acc[11] += xv * wv.w;
    }
    #pragma unroll
    for (int i = 0; i < 12; i++) {
        #pragma unroll
        for (int o = 16; o > 0; o >>= 1)
            acc[i] += __shfl_xor_sync(0xffffffffu, acc[i], o);
    }
    __shared__ float wr[4][12];
    int wid = tid >> 5, lane = tid & 31;
    if (lane == 0) {
        #pragma unroll
        for (int i = 0; i < 12; i++) wr[wid][i] = acc[i];
    }
    __syncthreads();
    if (tid < 12) {
        float s = wr[0][tid] + wr[1][tid] + wr[2][tid] + wr[3][tid];
        if (tid < 4)      g_q[row * 4 + tid]       = tanhf(s + bq[tid]);
        else if (tid < 8) g_k[row * 4 + (tid - 4)] = tanhf(s + bk[tid - 4]);
        else              g_v[row * 4 + (tid - 8)] = s + bv[tid - 8];
    }
}

// ---------------------------------------------------------------------------
// Fused scores + softmax + attended + output projection. One block per (b,i).
// ---------------------------------------------------------------------------
__global__ void __launch_bounds__(256) attn_kernel(
        float* __restrict__ out, float* __restrict__ attn,
        const float* __restrict__ Wout, const float* __restrict__ bout) {
    int row = blockIdx.x;
    int tid = threadIdx.x;  // 256
    int b = row / SS;
    int wid = tid >> 5, lane = tid & 31;

    __shared__ float Csh[81];
    __shared__ float qsh[4];
    __shared__ float rbuf[8];
    __shared__ float wsum[8][4];
    __shared__ float att4[4];

    if (tid < 81) Csh[tid] = g_C[tid];
    if (tid < 4)  qsh[tid] = g_q[row * 4 + tid];

    // Hoist k and v loads before the sync: 4 independent LDGs in flight (MLP=4).
    const float4* kp = (const float4*)(g_k + (b * SS + tid) * 4);
    const float4* vp = (const float4*)(g_v + (b * SS + tid) * 4);
    float4 kk0 = __ldg(kp);
    float4 kk1 = __ldg(kp + 256);
    float4 vv0 = __ldg(vp);
    float4 vv1 = __ldg(vp + 256);
    __syncthreads();

    float q0 = qsh[0], q1 = qsh[1], q2 = qsh[2], q3 = qsh[3];

    float sco[2];
    #pragma unroll
    for (int r = 0; r < 2; r++) {
        float4 kk = (r == 0) ? kk0 : kk1;
        float a0 = ftanh(q0 + kk.x);
        float a1 = ftanh(q1 + kk.y);
        float a2 = ftanh(q2 + kk.z);
        float a3 = ftanh(q3 + kk.w);
        float c0, s0, c1, s1, c2, s2, c3, s3;
        __sincosf(a0, &s0, &c0);   // |a| < 1: MUFU fast path, ~2^-21 abs err
        __sincosf(a1, &s1, &c1);
        __sincosf(a2, &s2, &c2);
        __sincosf(a3, &s3, &c3);

        // total = sum_t C[t] * v0[t0] v1[t1] v2[t2] v3[t3], v = (1, c, s);
        // explicit Horner with the *1 terms eliminated (80 FMA).
        float B0[3];
        #pragma unroll
        for (int t0 = 0; t0 < 3; t0++) {
            float B1[3];
            #pragma unroll
            for (int t1 = 0; t1 < 3; t1++) {
                const float* Cp = Csh + ((t0 * 3 + t1) * 3) * 3;
                float A20 = Cp[0] + Cp[1] * c3 + Cp[2] * s3;
                float A21 = Cp[3] + Cp[4] * c3 + Cp[5] * s3;
                float A22 = Cp[6] + Cp[7] * c3 + Cp[8] * s3;
                B1[t1] = A20 + A21 * c2 + A22 * s2;
            }
            B0[t0] = B1[0] + B1[1] * c1 + B1[2] * s1;
        }
        float total = B0[0] + B0[1] * c0 + B0[2] * s0;
        sco[r] = 0.5f * total;  // scores / sqrt(N_QUBITS)
    }

    // --- softmax: max ---
    float m = fmaxf(sco[0], sco[1]);
    #pragma unroll
    for (int o = 16; o > 0; o >>= 1) m = fmaxf(m, __shfl_xor_sync(0xffffffffu, m, o));
    if (lane == 0) rbuf[wid] = m;
    __syncthreads();
    if (tid == 0) {
        float mm = rbuf[0];
        #pragma unroll
        for (int w = 1; w < 8; w++) mm = fmaxf(mm, rbuf[w]);
        rbuf[0] = mm;
    }
    __syncthreads();
    float M = rbuf[0];

    float e0 = __expf(sco[0] - M);
    float e1 = __expf(sco[1] - M);
    float ps = e0 + e1;
    #pragma unroll
    for (int o = 16; o > 0; o >>= 1) ps += __shfl_xor_sync(0xffffffffu, ps, o);
    __syncthreads();  // all threads have read M before rbuf reuse
    if (lane == 0) rbuf[wid] = ps;
    __syncthreads();
    if (tid == 0) {
        float s = 0.f;
        #pragma unroll
        for (int w = 0; w < 8; w++) s += rbuf[w];
        rbuf[0] = __fdividef(1.0f, s);
    }
    __syncthreads();
    float inv = rbuf[0];

    float p0 = e0 * inv, p1 = e1 * inv;
    // Issue probability stores early so STG overlaps the reduction tree below.
    attn[row * SS + tid]       = p0;
    attn[row * SS + tid + 256] = p1;

    // --- attended = sum_j p_j * v_j ---
    float av[4];
    av[0] = p0 * vv0.x + p1 * vv1.x;
    av[1] = p0 * vv0.y + p1 * vv1.y;
    av[2] = p0 * vv0.z + p1 * vv1.z;
    av[3] = p0 * vv0.w + p1 * vv1.w;
    #pragma unroll
    for (int i = 0; i < 4; i++) {
        #pragma unroll
        for (int o = 16; o > 0; o >>= 1)
            av[i] += __shfl_xor_sync(0xffffffffu, av[i], o);
    }
    if (lane == 0) {
        #pragma unroll
        for (int i = 0; i < 4; i++) wsum[wid][i] = av[i];
    }
    __syncthreads();
    if (tid < 4) {
        float s = 0.f;
        #pragma unroll
        for (int w = 0; w < 8; w++) s += wsum[w][tid];
        att4[tid] = s;
    }
    __syncthreads();

    // --- out = attended @ Wout + bout ---
    float w0 = att4[0], w1 = att4[1], w2 = att4[2], w3 = att4[3];
    #pragma unroll
    for (int r = 0; r < 2; r++) {
        int e = tid + r * 256;
        float o = __ldg(bout + e)
                + w0 * __ldg(Wout + e)
                + w1 * __ldg(Wout + EE + e)
                + w2 * __ldg(Wout + 2 * EE + e)
                + w3 * __ldg(Wout + 3 * EE + e);
        out[row * EE + e] = o;
    }
}

extern "C" void kernel_launch(void* const* d_in, const int* in_sizes, int n_in,
                              void* d_out, int out_size) {
    const float* x    = (const float*)d_in[0];
    const float* Wq   = (const float*)d_in[1];
    const float* bq   = (const float*)d_in[2];
    const float* Wk   = (const float*)d_in[3];
    const float* bk   = (const float*)d_in[4];
    const float* Wv   = (const float*)d_in[5];
    const float* bv   = (const float*)d_in[6];
    const float* qw   = (const float*)d_in[7];
    const float* Wout = (const float*)d_in[8];
    const float* bout = (const float*)d_in[9];
    float* out  = (float*)d_out;
    float* attn = out + (size_t)BB * SS * EE;

    setup_kernel<<<1, 256>>>(qw);
    qkv_kernel<<<NROWS, 128>>>(x, Wq, bq, Wk, bk, Wv, bv);
    attn_kernel<<<NROWS, 256>>>(out, attn, Wout, bout);
}

// round 5
// speedup vs baseline: 1.1106x; 1.1106x over previous
#include <cuda_runtime.h>

#define NQ 4
#define QDIM 16
#define BB 4
#define SS 512
#define EE 512
#define NROWS (BB*SS)

// Scratch (no allocations allowed):
__device__ __align__(16) float g_q[NROWS * 4];
__device__ __align__(16) float g_k[NROWS * 4];
__device__ __align__(16) float g_v[NROWS * 4];
__device__ float g_C[81];

struct c2 { float x, y; };
__device__ __forceinline__ c2 cmul(c2 a, c2 b) { return {a.x*b.x - a.y*b.y, a.x*b.y + a.y*b.x}; }
__device__ __forceinline__ c2 cadd(c2 a, c2 b) { return {a.x + b.x, a.y + b.y}; }

// Accurate tanh via ex2: arg in (-2,2), exp(2x) in [e^-4,e^4], no overflow.
__device__ __forceinline__ float ftanh(float x) {
    float e2 = __expf(2.0f * x);
    return __fdividef(e2 - 1.0f, e2 + 1.0f);
}

// ---- packed f32x2 helpers (FFMA2: PTX-only, ptxas won't auto-fuse) ----
typedef unsigned long long u64c;
__device__ __forceinline__ u64c pk2(float lo, float hi) {
    u64c r; asm("mov.b64 %0, {%1, %2};" : "=l"(r) : "f"(lo), "f"(hi)); return r;
}
__device__ __forceinline__ void upk2(u64c v, float& lo, float& hi) {
    asm("mov.b64 {%0, %1}, %2;" : "=f"(lo), "=f"(hi) : "l"(v));
}
__device__ __forceinline__ u64c fma2(u64c a, u64c b, u64c c) {
    u64c d; asm("fma.rn.f32x2 %0, %1, %2, %3;" : "=l"(d) : "l"(a), "l"(b), "l"(c)); return d;
}

// ---------------------------------------------------------------------------
// Setup body (128 threads): build U (16x16 circuit unitary), A = Re(U^H Z U),
// collapse to the 81-coefficient multilinear tensor C.
// Wire w <-> bit position (3 - w) (numpy row-major flatten of (2,2,2,2)).
// ---------------------------------------------------------------------------
__device__ void setup_body(const float* __restrict__ qw, int tid) {
    __shared__ c2 G[8][4];        // 8 Rot gates (layer*4 + wire), 2x2 each
    __shared__ c2 U[QDIM][QDIM];  // U[m][col]
    __shared__ float A[QDIM][QDIM];

    if (tid < 8) {
        float a = qw[tid * 3 + 0] * 0.5f;
        float b = qw[tid * 3 + 1] * 0.5f;
        float c = qw[tid * 3 + 2] * 0.5f;
        float ca = cosf(a), sa = sinf(a);
        float cb = cosf(b), sb = sinf(b);
        float zc = cosf(c), zs = sinf(c);
        // RX = [[ca, -i sa], [-i sa, ca]]
        c2 X00 = {ca, 0.f}, X01 = {0.f, -sa}, X10 = {0.f, -sa}, X11 = {ca, 0.f};
        // M = RY @ RX  (RY real)
        c2 M00 = {cb * X00.x - sb * X10.x, cb * X00.y - sb * X10.y};
        c2 M01 = {cb * X01.x - sb * X11.x, cb * X01.y - sb * X11.y};
        c2 M10 = {sb * X00.x + cb * X10.x, sb * X00.y + cb * X10.y};
        c2 M11 = {sb * X01.x + cb * X11.x, sb * X01.y + cb * X11.y};
        // G = RZ @ M, RZ = diag(e^{-ic}, e^{+ic})
        c2 e0 = {zc, -zs}, e1 = {zc, zs};
        G[tid][0] = cmul(e0, M00); G[tid][1] = cmul(e0, M01);
        G[tid][2] = cmul(e1, M10); G[tid][3] = cmul(e1, M11);
    }
    __syncthreads();

    if (tid < QDIM) {
        c2 amp[QDIM];
        #pragma unroll
        for (int d = 0; d < QDIM; d++) amp[d] = {0.f, 0.f};
        amp[tid] = {1.f, 0.f};
        #pragma unroll
        for (int layer = 0; layer < 2; layer++) {
            #pragma unroll
            for (int w = 0; w < 4; w++) {
                c2 g00 = G[layer * 4 + w][0], g01 = G[layer * 4 + w][1];
                c2 g10 = G[layer * 4 + w][2], g11 = G[layer * 4 + w][3];
                int mask = 1 << (3 - w);
                #pragma unroll
                for (int d = 0; d < QDIM; d++) {
                    if (d & mask) continue;
                    c2 x0 = amp[d], x1 = amp[d | mask];
                    amp[d]        = cadd(cmul(g00, x0), cmul(g01, x1));
                    amp[d | mask] = cadd(cmul(g10, x0), cmul(g11, x1));
                }
            }
            // CNOTs (ctrl,tgt): (0,1),(1,2),(2,3),(3,0) -> msb-first bitmasks
            const int cm[4] = {8, 4, 2, 1};
            const int tm[4] = {4, 2, 1, 8};
            #pragma unroll
            for (int p = 0; p < 4; p++) {
                #pragma unroll
                for (int d = 0; d < QDIM; d++) {
                    if ((d & cm[p]) && !(d & tm[p])) {
                        c2 t = amp[d];
                        amp[d] = amp[d | tm[p]];
                        amp[d | tm[p]] = t;
                    }
                }
            }
        }
        #pragma unroll
        for (int m = 0; m < QDIM; m++) U[m][tid] = amp[m];
    }
    __syncthreads();

    // A[d][e] = Re( sum_m conj(U[m][d]) * z_m * U[m][e] ),  z_m = 4 - 2 popc(m)
    #pragma unroll
    for (int it = 0; it < 2; it++) {
        int idx = tid + it * 128;
        int d = idx >> 4, e = idx & 15;
        float s = 0.f;
        #pragma unroll
        for (int m = 0; m < QDIM; m++) {
            float z = 4.0f - 2.0f * (float)__popc(m);
            s += z * (U[m][d].x * U[m][e].x + U[m][d].y * U[m][e].y);
        }
        A[d][e] = s;
    }
    __syncthreads();

    // C[t0..t3], v=(1,cos a,sin a) per wire.
    // t=0: e_w=d_w, coeff 1/2; t=1: e_w=d_w, coeff (+/-)1/2 by d_w; t=2: e_w=1-d_w, 1/2.
    if (tid < 81) {
        int t0 = tid / 27, t1 = (tid / 9) % 3, t2 = (tid / 3) % 3, t3 = tid % 3;
        int tw[4] = {t0, t1, t2, t3};
        int xmask = 0, m1 = 0;
        #pragma unroll
        for (int w = 0; w < 4; w++) {
            if (tw[w] == 2) xmask |= 1 << (3 - w);
            if (tw[w] == 1) m1   |= 1 << (3 - w);
        }
        float s = 0.f;
        #pragma unroll
        for (int d = 0; d < QDIM; d++) {
            float sgn = (__popc(d & m1) & 1) ? -1.0f : 1.0f;
            s += sgn * A[d][d ^ xmask];
        }
        g_C[tid] = s * 0.0625f;  // (1/2)^4
    }
}

// ---------------------------------------------------------------------------
// Merged setup + QKV: block 0 does setup; blocks 1..NROWS do one (b,s) row
// of the QKV projection each. Setup hides under the qkv wave instead of
// occupying a serial 8us grid=1 slot.
// ---------------------------------------------------------------------------
__global__ void __launch_bounds__(128) qkv_setup_kernel(
        const float* __restrict__ x,
        const float* __restrict__ Wq, const float* __restrict__ bq,
        const float* __restrict__ Wk, const float* __restrict__ bk,
        const float* __restrict__ Wv, const float* __restrict__ bv,
        const float* __restrict__ qw) {
    int tid = threadIdx.x;  // 128
    if (blockIdx.x == 0) { setup_body(qw, tid); return; }

    int row = blockIdx.x - 1;
    const float* xr = x + row * EE;

    float acc[12];
    #pragma unroll
    for (int i = 0; i < 12; i++) acc[i] = 0.f;

    #pragma unroll 2
    for (int e = tid; e < EE; e += 128) {
        float xv = __ldg(xr + e);
        float4 wq = __ldg((const float4*)(Wq + e * 4));
        float4 wk = __ldg((const float4*)(Wk + e * 4));
        float4 wv = __ldg((const float4*)(Wv + e * 4));
        acc[0] += xv * wq.x; acc[1] += xv * wq.y; acc[2]  += xv * wq.z; acc[3]  += xv * wq.w;
        acc[4] += xv * wk.x; acc[5] += xv * wk.y; acc[6]  += xv * wk.z; acc[7]  += xv * wk.w;
        acc[8] += xv * wv.x; acc[9] += xv * wv.y; acc[10] += xv * wv.z; acc[11] += xv * wv.w;
    }
    #pragma unroll
    for (int i = 0; i < 12; i++) {
        #pragma unroll
        for (int o = 16; o > 0; o >>= 1)
            acc[i] += __shfl_xor_sync(0xffffffffu, acc[i], o);
    }
    __shared__ float wr[4][12];
    int wid = tid >> 5, lane = tid & 31;
    if (lane == 0) {
        #pragma unroll
        for (int i = 0; i < 12; i++) wr[wid][i] = acc[i];
    }
    __syncthreads();
    if (tid < 12) {
        float s = wr[0][tid] + wr[1][tid] + wr[2][tid] + wr[3][tid];
        if (tid < 4)      g_q[row * 4 + tid]       = tanhf(s + bq[tid]);
        else if (tid < 8) g_k[row * 4 + (tid - 4)] = tanhf(s + bk[tid - 4]);
        else              g_v[row * 4 + (tid - 8)] = s + bv[tid - 8];
    }
}

// ---------------------------------------------------------------------------
// Fused scores + softmax + attended + output projection. One block per (b,i).
// Both j-pairs per thread are computed simultaneously with packed FFMA2.
// ---------------------------------------------------------------------------
__global__ void __launch_bounds__(256) attn_kernel(
        float* __restrict__ out, float* __restrict__ attn,
        const float* __restrict__ Wout, const float* __restrict__ bout) {
    int row = blockIdx.x;
    int tid = threadIdx.x;  // 256
    int b = row / SS;
    int wid = tid >> 5, lane = tid & 31;

    __shared__ __align__(8) float2 Csh2[81];  // coefficients duplicated (C,C)
    __shared__ float qsh[4];
    __shared__ float rbuf[8];
    __shared__ float wsum[8][4];
    __shared__ float att4[4];

    if (tid < 81) { float c = g_C[tid]; Csh2[tid] = make_float2(c, c); }
    if (tid < 4)  qsh[tid] = g_q[row * 4 + tid];

    // Hoist k and v loads before the sync: 4 independent LDGs in flight.
    const float4* kp = (const float4*)(g_k + (b * SS + tid) * 4);
    const float4* vp = (const float4*)(g_v + (b * SS + tid) * 4);
    float4 kk0 = __ldg(kp);
    float4 kk1 = __ldg(kp + 256);
    float4 vv0 = __ldg(vp);
    float4 vv1 = __ldg(vp + 256);
    __syncthreads();

    float q0 = qsh[0], q1 = qsh[1], q2 = qsh[2], q3 = qsh[3];

    // angles + sin/cos for both j's (scalar MUFU path)
    float a0A = ftanh(q0 + kk0.x), a1A = ftanh(q1 + kk0.y);
    float a2A = ftanh(q2 + kk0.z), a3A = ftanh(q3 + kk0.w);
    float a0B = ftanh(q0 + kk1.x), a1B = ftanh(q1 + kk1.y);
    float a2B = ftanh(q2 + kk1.z), a3B = ftanh(q3 + kk1.w);
    float c0A, s0A, c1A, s1A, c2A, s2A, c3A, s3A;
    float c0B, s0B, c1B, s1B, c2B, s2B, c3B, s3B;
    __sincosf(a0A, &s0A, &c0A); __sincosf(a1A, &s1A, &c1A);
    __sincosf(a2A, &s2A, &c2A); __sincosf(a3A, &s3A, &c3A);
    __sincosf(a0B, &s0B, &c0B); __sincosf(a1B, &s1B, &c1B);
    __sincosf(a2B, &s2B, &c2B); __sincosf(a3B, &s3B, &c3B);

    // pack (j0, j1) lanes
    u64c c0p = pk2(c0A, c0B), s0p = pk2(s0A, s0B);
    u64c c1p = pk2(c1A, c1B), s1p = pk2(s1A, s1B);
    u64c c2p = pk2(c2A, c2B), s2p = pk2(s2A, s2B);
    u64c c3p = pk2(c3A, c3B), s3p = pk2(s3A, s3B);

    // total = sum_t C[t] * v0[t0] v1[t1] v2[t2] v3[t3], v = (1, c, s)
    // 80 packed FFMA2 covering both j's.
    const u64c* Cd = (const u64c*)Csh2;
    u64c B0[3];
    #pragma unroll
    for (int t0 = 0; t0 < 3; t0++) {
        u64c B1[3];
        #pragma unroll
        for (int t1 = 0; t1 < 3; t1++) {
            int base = (t0 * 3 + t1) * 9;
            u64c A20 = fma2(Cd[base + 2], s3p, fma2(Cd[base + 1], c3p, Cd[base + 0]));
            u64c A21 = fma2(Cd[base + 5], s3p, fma2(Cd[base + 4], c3p, Cd[base + 3]));
            u64c A22 = fma2(Cd[base + 8], s3p, fma2(Cd[base + 7], c3p, Cd[base + 6]));
            B1[t1] = fma2(A22, s2p, fma2(A21, c2p, A20));
        }
        B0[t0] = fma2(B1[2], s1p, fma2(B1[1], c1p, B1[0]));
    }
    u64c totp = fma2(B0[2], s0p, fma2(B0[1], c0p, B0[0]));
    float t0f, t1f;
    upk2(totp, t0f, t1f);
    float sco0 = 0.5f * t0f;   // scores / sqrt(N_QUBITS)
    float sco1 = 0.5f * t1f;

    // --- softmax: max ---
    float m = fmaxf(sco0, sco1);
    #pragma unroll
    for (int o = 16; o > 0; o >>= 1) m = fmaxf(m, __shfl_xor_sync(0xffffffffu, m, o));
    if (lane == 0) rbuf[wid] = m;
    __syncthreads();
    if (tid == 0) {
        float mm = rbuf[0];
        #pragma unroll
        for (int w = 1; w < 8; w++) mm = fmaxf(mm, rbuf[w]);
        rbuf[0] = mm;
    }
    __syncthreads();
    float M = rbuf[0];

    float e0 = __expf(sco0 - M);
    float e1 = __expf(sco1 - M);
    float ps = e0 + e1;
    #pragma unroll
    for (int o = 16; o > 0; o >>= 1) ps += __shfl_xor_sync(0xffffffffu, ps, o);
    __syncthreads();  // all threads have read M before rbuf reuse
    if (lane == 0) rbuf[wid] = ps;
    __syncthreads();
    if (tid == 0) {
        float s = 0.f;
        #pragma unroll
        for (int w = 0; w < 8; w++) s += rbuf[w];
        rbuf[0] = __fdividef(1.0f, s);
    }
    __syncthreads();
    float inv = rbuf[0];

    float p0 = e0 * inv, p1 = e1 * inv;
    // Issue probability stores early so STG overlaps the reduction tree below.
    attn[row * SS + tid]       = p0;
    attn[row * SS + tid + 256] = p1;

    // --- attended = sum_j p_j * v_j ---
    float av[4];
    av[0] = p0 * vv0.x + p1 * vv1.x;
    av[1] = p0 * vv0.y + p1 * vv1.y;
    av[2] = p0 * vv0.z + p1 * vv1.z;
    av[3] = p0 * vv0.w + p1 * vv1.w;
    #pragma unroll
    for (int i = 0; i < 4; i++) {
        #pragma unroll
        for (int o = 16; o > 0; o >>= 1)
            av[i] += __shfl_xor_sync(0xffffffffu, av[i], o);
    }
    if (lane == 0) {
        #pragma unroll
        for (int i = 0; i < 4; i++) wsum[wid][i] = av[i];
    }
    __syncthreads();
    if (tid < 4) {
        float s = 0.f;
        #pragma unroll
        for (int w = 0; w < 8; w++) s += wsum[w][tid];
        att4[tid] = s;
    }
    __syncthreads();

    // --- out = attended @ Wout + bout ---
    float w0 = att4[0], w1 = att4[1], w2 = att4[2], w3 = att4[3];
    #pragma unroll
    for (int r = 0; r < 2; r++) {
        int e = tid + r * 256;
        float o = __ldg(bout + e)
                + w0 * __ldg(Wout + e)
                + w1 * __ldg(Wout + EE + e)
                + w2 * __ldg(Wout + 2 * EE + e)
                + w3 * __ldg(Wout + 3 * EE + e);
        out[row * EE + e] = o;
    }
}

extern "C" void kernel_launch(void* const* d_in, const int* in_sizes, int n_in,
                              void* d_out, int out_size) {
    const float* x    = (const float*)d_in[0];
    const float* Wq   = (const float*)d_in[1];
    const float* bq   = (const float*)d_in[2];
    const float* Wk   = (const float*)d_in[3];
    const float* bk   = (const float*)d_in[4];
    const float* Wv   = (const float*)d_in[5];
    const float* bv   = (const float*)d_in[6];
    const float* qw   = (const float*)d_in[7];
    const float* Wout = (const float*)d_in[8];
    const float* bout = (const float*)d_in[9];
    float* out  = (float*)d_out;
    float* attn = out + (size_t)BB * SS * EE;

    qkv_setup_kernel<<<NROWS + 1, 128>>>(x, Wq, bq, Wk, bk, Wv, bv, qw);
    attn_kernel<<<NROWS, 256>>>(out, attn, Wout, bout);
}